// round 4
// baseline (speedup 1.0000x reference)
#include <cuda_runtime.h>
#include <cuda_bf16.h>

// SqRL fused single-launch kernel, two block roles:
//  Role H (blockIdx.y < 256): one CTA per (ring r, image). The output row is
//    5 constant runs + 1 aligned copy + 1 reversed copy + 4-wide wrap:
//      [0,i)      = cTL            (TL corner)
//      [i,b1)     = row_i[j]       (top edge, identical index -> aligned copy)
//      [b1,b2)    = cTR
//      [b2,b3)    vertical (right edge) -> role V
//      [b3,b4)    = cBR
//      [b4,b5)    = row_b1[1533-j] (bottom edge, reversed copy)
//      [b5,b6)    = cBL
//      [b6,b7)    vertical (left edge) -> role V
//      [b7,2044)  = cTL
//      [2044,2048)= copies of [0,4)
//    Bounds computed once per CTA (uniform); fills/copies are float4 loops.
//  Role V (blockIdx.y >= 256): masked 32x32 smem transpose of the two
//    triangular column regions:
//      out[r][511+row]  = x[row][256+r]   (|row-255| <= r)
//      out[r][2044-row] = x[row][255-r]   (|row-256| <= r)

#define HH  512
#define HR  256
#define RL  2048

__device__ __forceinline__ void fill_run(float* __restrict__ o, int lo, int hi,
                                         float v, int t) {
    if (lo >= hi) return;
    int a = (lo + 3) & ~3; if (a > hi) a = hi;
    int b = hi & ~3;       if (b < a) b = a;
    if (t < a - lo) o[lo + t] = v;
    const float4 vv = make_float4(v, v, v, v);
    for (int j = a + 4 * t; j < b; j += 1024)
        *reinterpret_cast<float4*>(o + j) = vv;
    if (t < hi - b) o[b + t] = v;
}

__global__ __launch_bounds__(256)
void sqrl_fused(const float* __restrict__ x, float* __restrict__ out) {
    const int t  = threadIdx.x;
    const int bc = blockIdx.z;
    const float* __restrict__ img = x + (size_t)bc * (HH * HH);

    if (blockIdx.y < HR) {
        // ─── Role H: one ring, one image ───
        const int r  = blockIdx.y;
        const int i  = (HR - 1) - r;
        const int el = 2 * r + 1;
        const int b1 = i + el;          // 256 + r
        const int b2 = b1 + 2 * i;      // 766 - r
        const int b3 = b2 + el;         // 767 + r
        const int b4 = b3 + 2 * i;      // 1277 - r
        const int b5 = b4 + el;         // 1278 + r
        const int b6 = b5 + 2 * i;      // 1788 - r
        const int b7 = b6 + el;         // 1789 + r

        float* __restrict__ orow = out + (((size_t)bc * HR) + (size_t)r) * RL;
        const float* __restrict__ rowi  = img + (size_t)i  * HH;
        const float* __restrict__ rowb1 = img + (size_t)b1 * HH;

        const float cTL = __ldg(rowi + i);
        const float cTR = __ldg(rowi + (HH - 1 - i));
        const float cBR = __ldg(rowb1 + b1);
        const float cBL = __ldg(rowb1 + i);

        fill_run(orow, 0,  i,    cTL, t);
        fill_run(orow, b1, b2,   cTR, t);
        fill_run(orow, b3, b4,   cBR, t);
        fill_run(orow, b5, b6,   cBL, t);
        fill_run(orow, b7, 2044, cTL, t);

        // top edge copy: out[j] = rowi[j], j in [i, b1); src/dst share index
        {
            int lo = i, hi = b1;
            int a = (lo + 3) & ~3; if (a > hi) a = hi;
            int b = hi & ~3;       if (b < a) b = a;
            if (t < a - lo) orow[lo + t] = __ldg(rowi + lo + t);
            for (int j = a + 4 * t; j < b; j += 1024)
                *reinterpret_cast<float4*>(orow + j) =
                    *reinterpret_cast<const float4*>(rowi + j);
            if (t < hi - b) orow[b + t] = __ldg(rowi + b + t);
        }

        // bottom edge reversed copy: out[j] = rowb1[1533 - j], j in [b4, b5)
        {
            int lo = b4, hi = b5;
            int a = (lo + 3) & ~3; if (a > hi) a = hi;
            int b = hi & ~3;       if (b < a) b = a;
            if (t < a - lo) orow[lo + t] = __ldg(rowb1 + 1533 - (lo + t));
            for (int j = a + 4 * t; j < b; j += 1024) {
                // cols [1530-j, 1533-j]; 1530-j is even -> 8B-aligned float2 loads
                const float2 lo2 = __ldg(reinterpret_cast<const float2*>(rowb1 + 1530 - j));
                const float2 hi2 = __ldg(reinterpret_cast<const float2*>(rowb1 + 1532 - j));
                *reinterpret_cast<float4*>(orow + j) =
                    make_float4(hi2.y, hi2.x, lo2.y, lo2.x);
            }
            if (t < hi - b) orow[b + t] = __ldg(rowb1 + 1533 - (b + t));
        }

        // wrap: out[2044+k] = out[k] = (k < i ? cTL : rowi[k])
        if (t < 4)
            orow[2044 + t] = (t < i) ? cTL : __ldg(rowi + t);
    } else {
        // ─── Role V: masked 32x32 transpose tile ───
        __shared__ float tile[32][33];
        const int v  = blockIdx.y - HR;        // 0..255
        const int R0 = (v >> 4) * 32;
        const int C0 = (v & 15) * 32;

        // early-out if tile misses both triangles
        if (C0 >= 256) {
            const int rmax = C0 - 256 + 31;
            if (R0 + 31 < 255 - rmax || R0 > 255 + rmax) return;
        } else {
            const int rmax = 255 - C0;
            if (R0 + 31 < 256 - rmax || R0 > 256 + rmax) return;
        }

        const int tx = t & 31;
        const int ty = t >> 5;

        #pragma unroll
        for (int k = 0; k < 4; ++k) {
            const int rowl = ty * 4 + k;
            tile[rowl][tx] = __ldg(img + (size_t)(R0 + rowl) * HH + C0 + tx);
        }
        __syncthreads();

        float* __restrict__ obase = out + ((size_t)bc * HR) * RL;
        const int row = R0 + tx;

        #pragma unroll
        for (int k = 0; k < 4; ++k) {
            const int u = ty * 4 + k;
            const float val = tile[tx][u];
            if (C0 >= 256) {
                const int r = C0 + u - 256;     // right edge ring
                if (row >= 255 - r && row <= 255 + r)
                    obase[(size_t)r * RL + 511 + row] = val;
            } else {
                const int r = 255 - (C0 + u);   // left edge ring
                if (row >= 256 - r && row <= 256 + r)
                    obase[(size_t)r * RL + 2044 - row] = val;
            }
        }
    }
}

extern "C" void kernel_launch(void* const* d_in, const int* in_sizes, int n_in,
                              void* d_out, int out_size) {
    const float* x = (const float*)d_in[0];
    float* out = (float*)d_out;
    const int bc = in_sizes[0] / (HH * HH);   // 16*32 = 512 images
    dim3 grid(1, 2 * HR, bc);                 // y: 256 rings + 256 transpose tiles
    sqrl_fused<<<grid, 256>>>(x, out);
}

// round 5
// speedup vs baseline: 1.6141x; 1.6141x over previous
#include <cuda_runtime.h>
#include <cuda_bf16.h>

// SqRL: table-driven gather (horizontal/corner segments) fused with a masked
// 32x32 smem transpose (vertical segments), one launch, 8 images per CTA.
//
// Ring r (0..255), i = 255-r, el = 2r+1, b1 = 256+r:
//   seg bounds: b2 = 766-r, b3 = 767+r (right edge, vertical)
//               b4 = 1277-r, b5 = 1278+r (bottom edge)
//               b6 = 1788-r, b7 = 1789+r (left edge, vertical)
// Vertical identities (handled by transpose role V):
//   out[r][511+row]  = x[row][256+r]  (|row-255| <= r)
//   out[r][2044-row] = x[row][255-r]  (|row-256| <= r)
// Everything else is in the 2MB static index table (vertical marked -1).

#define HH    512
#define HR    256
#define RL    2048
#define IMGS  8

__device__ int g_idx[HR * RL];   // 2 MB static scratch (allowed)

__global__ __launch_bounds__(256)
void sqrl_init_idx() {
    const int r  = blockIdx.x >> 1;
    const int jb = blockIdx.x & 1;
    const int i  = (HR - 1) - r;
    const int el = 2 * r + 1;
    const int b1 = i + el;
    const int b2 = b1 + 2 * i;
    const int b3 = b2 + el;
    const int b4 = b3 + 2 * i;
    const int b5 = b4 + el;
    const int b6 = b5 + 2 * i;
    const int b7 = b6 + el;
    const int base = jb * 1024 + threadIdx.x * 4;
    #pragma unroll
    for (int k = 0; k < 4; ++k) {
        const int j  = base + k;
        const int jp = (j >= 2044) ? j - 2044 : j;   // tail wrap
        int v;
        if (jp < i)        v = i * HH + i;                   // TL corner
        else if (jp < b1)  v = i * HH + jp;                  // top edge
        else if (jp < b2)  v = i * HH + (HH - 1 - i);        // TR corner
        else if (jp < b3)  v = -1;                           // right edge -> V
        else if (jp < b4)  v = b1 * HH + b1;                 // BR corner
        else if (jp < b5)  v = b1 * HH + (b1 - (jp - b4));   // bottom edge (rev)
        else if (jp < b6)  v = b1 * HH + i;                  // BL corner
        else if (jp < b7)  v = -1;                           // left edge -> V
        else               v = i * HH + i;                   // trailing TL corner
        g_idx[r * RL + j] = v;
    }
}

__global__ __launch_bounds__(256)
void sqrl_main(const float* __restrict__ x, float* __restrict__ out, int images) {
    const int t   = threadIdx.x;
    const int bc0 = blockIdx.y * IMGS;
    int nim = images - bc0; if (nim > IMGS) nim = IMGS;

    if (blockIdx.x < 2 * HR) {
        // ─── Role H: table gather. One (ring, half-row) x 8 images. ───
        const int r  = blockIdx.x >> 1;
        const int jb = blockIdx.x & 1;
        const int4 id = *reinterpret_cast<const int4*>(g_idx + r * RL + jb * 1024 + t * 4);

        const int mn = min(min(id.x, id.y), min(id.z, id.w));
        const int mx = max(max(id.x, id.y), max(id.z, id.w));
        if (mx < 0) return;   // fully vertical: role V owns these columns

        const float* __restrict__ img  = x + (size_t)bc0 * (HH * HH);
        float* __restrict__       orow = out + ((size_t)bc0 * HR + (size_t)r) * RL
                                             + jb * 1024 + t * 4;
        if (mn >= 0) {
            for (int kk = 0; kk < nim; ++kk) {
                const float4 v = make_float4(__ldg(img + id.x), __ldg(img + id.y),
                                             __ldg(img + id.z), __ldg(img + id.w));
                *reinterpret_cast<float4*>(orow) = v;
                img  += HH * HH;
                orow += (size_t)HR * RL;
            }
        } else {
            // mixed block at a vertical-segment boundary (rare)
            for (int kk = 0; kk < nim; ++kk) {
                if (id.x >= 0) orow[0] = __ldg(img + id.x);
                if (id.y >= 0) orow[1] = __ldg(img + id.y);
                if (id.z >= 0) orow[2] = __ldg(img + id.z);
                if (id.w >= 0) orow[3] = __ldg(img + id.w);
                img  += HH * HH;
                orow += (size_t)HR * RL;
            }
        }
    } else {
        // ─── Role V: masked 32x32 transpose tile x 8 images. ───
        const int v  = blockIdx.x - 2 * HR;   // 0..255
        const int R0 = (v >> 4) * 32;
        const int C0 = (v & 15) * 32;

        // early-out if the tile misses both triangles (uniform across images)
        if (C0 >= 256) {
            const int rmax = C0 - 256 + 31;
            if (R0 + 31 < 255 - rmax || R0 > 255 + rmax) return;
        } else {
            const int rmax = 255 - C0;
            if (R0 + 31 < 256 - rmax || R0 > 256 + rmax) return;
        }

        __shared__ float tile[32][33];
        const int tx = t & 31;
        const int ty = t >> 5;

        for (int kk = 0; kk < nim; ++kk) {
            const float* __restrict__ im = x + (size_t)(bc0 + kk) * (HH * HH);
            #pragma unroll
            for (int k = 0; k < 4; ++k) {
                const int rowl = ty * 4 + k;
                tile[rowl][tx] = __ldg(im + (size_t)(R0 + rowl) * HH + C0 + tx);
            }
            __syncthreads();

            float* __restrict__ obase = out + (size_t)(bc0 + kk) * HR * RL;
            const int row = R0 + tx;
            #pragma unroll
            for (int k = 0; k < 4; ++k) {
                const int u   = ty * 4 + k;
                const float w = tile[tx][u];
                if (C0 >= 256) {
                    const int rr = C0 + u - 256;            // right edge ring
                    if (row >= 255 - rr && row <= 255 + rr)
                        obase[(size_t)rr * RL + 511 + row] = w;
                } else {
                    const int rr = 255 - (C0 + u);          // left edge ring
                    if (row >= 256 - rr && row <= 256 + rr)
                        obase[(size_t)rr * RL + 2044 - row] = w;
                }
            }
            __syncthreads();
        }
    }
}

extern "C" void kernel_launch(void* const* d_in, const int* in_sizes, int n_in,
                              void* d_out, int out_size) {
    const float* x = (const float*)d_in[0];
    float* out = (float*)d_out;
    const int images = in_sizes[0] / (HH * HH);          // 512
    const int groups = (images + IMGS - 1) / IMGS;       // 64

    sqrl_init_idx<<<2 * HR, 256>>>();

    dim3 grid(2 * HR + 256, groups);   // x: 512 H tasks + 256 V tiles
    sqrl_main<<<grid, 256>>>(x, out, images);
}

// round 6
// speedup vs baseline: 1.6341x; 1.0124x over previous
#include <cuda_runtime.h>
#include <cuda_bf16.h>

// SqRL fused, single launch: inline-classified gather (horizontal/corner
// segments, classification done ONCE per thread then reused for 8 images)
// + pipelined masked 32x32 smem transpose (vertical segments).
//
// Ring r (0..255), i = 255-r, el = 2r+1, b1 = 256+r:
//   b2 = 766-r, b3 = 767+r (right edge, vertical)
//   b4 = 1277-r, b5 = 1278+r (bottom edge)
//   b6 = 1788-r, b7 = 1789+r (left edge, vertical)
// Vertical identities (role V):
//   out[r][511+row]  = x[row][256+r]  (|row-255| <= r)
//   out[r][2044-row] = x[row][255-r]  (|row-256| <= r)

#define HH    512
#define HR    256
#define RL    2048
#define IMGS  8

__global__ __launch_bounds__(256)
void sqrl_main(const float* __restrict__ x, float* __restrict__ out, int images) {
    const int t   = threadIdx.x;
    const int bc0 = blockIdx.y * IMGS;
    int nim = images - bc0; if (nim > IMGS) nim = IMGS;

    if (blockIdx.x < 2 * HR) {
        // ─── Role H: inline-classified gather, one (ring, half-row) x 8 images ───
        const int r  = blockIdx.x >> 1;
        const int jb = blockIdx.x & 1;
        const int i  = (HR - 1) - r;
        const int el = 2 * r + 1;
        const int b1 = i + el;
        const int b2 = b1 + 2 * i;
        const int b3 = b2 + el;
        const int b4 = b3 + 2 * i;
        const int b5 = b4 + el;
        const int b6 = b5 + 2 * i;
        const int b7 = b6 + el;

        int idv[4];
        const int base = jb * 1024 + t * 4;
        #pragma unroll
        for (int k = 0; k < 4; ++k) {
            const int j  = base + k;
            const int jp = (j >= 2044) ? j - 2044 : j;   // tail wrap
            int v;
            if (jp < i)        v = i * HH + i;                   // TL corner
            else if (jp < b1)  v = i * HH + jp;                  // top edge
            else if (jp < b2)  v = i * HH + (HH - 1 - i);        // TR corner
            else if (jp < b3)  v = -1;                           // right edge -> V
            else if (jp < b4)  v = b1 * HH + b1;                 // BR corner
            else if (jp < b5)  v = b1 * HH + (b1 - (jp - b4));   // bottom edge (rev)
            else if (jp < b6)  v = b1 * HH + i;                  // BL corner
            else if (jp < b7)  v = -1;                           // left edge -> V
            else               v = i * HH + i;                   // trailing TL corner
            idv[k] = v;
        }

        const int mn = min(min(idv[0], idv[1]), min(idv[2], idv[3]));
        const int mx = max(max(idv[0], idv[1]), max(idv[2], idv[3]));
        if (mx < 0) return;   // fully vertical 4-block: role V owns it

        const float* __restrict__ img  = x + (size_t)bc0 * (HH * HH);
        float* __restrict__       orow = out + ((size_t)bc0 * HR + (size_t)r) * RL + base;

        if (mn >= 0) {
            #pragma unroll 2
            for (int kk = 0; kk < nim; ++kk) {
                const float4 v = make_float4(__ldg(img + idv[0]), __ldg(img + idv[1]),
                                             __ldg(img + idv[2]), __ldg(img + idv[3]));
                *reinterpret_cast<float4*>(orow) = v;
                img  += HH * HH;
                orow += (size_t)HR * RL;
            }
        } else {
            // mixed block straddling a vertical-segment boundary (rare)
            for (int kk = 0; kk < nim; ++kk) {
                if (idv[0] >= 0) orow[0] = __ldg(img + idv[0]);
                if (idv[1] >= 0) orow[1] = __ldg(img + idv[1]);
                if (idv[2] >= 0) orow[2] = __ldg(img + idv[2]);
                if (idv[3] >= 0) orow[3] = __ldg(img + idv[3]);
                img  += HH * HH;
                orow += (size_t)HR * RL;
            }
        }
    } else {
        // ─── Role V: masked 32x32 transpose, software-pipelined over 8 images ───
        const int v  = blockIdx.x - 2 * HR;   // 0..255
        const int R0 = (v >> 4) * 32;
        const int C0 = (v & 15) * 32;

        // early-out if the tile misses both triangles (image-independent)
        if (C0 >= 256) {
            const int rmax = C0 - 256 + 31;
            if (R0 + 31 < 255 - rmax || R0 > 255 + rmax) return;
        } else {
            const int rmax = 255 - C0;
            if (R0 + 31 < 256 - rmax || R0 > 256 + rmax) return;
        }

        __shared__ float tile[32][33];
        const int tx = t & 31;
        const int ty = t >> 5;
        const int row = R0 + tx;

        // prefetch image 0
        float rv[4];
        {
            const float* __restrict__ im = x + (size_t)bc0 * (HH * HH);
            #pragma unroll
            for (int k = 0; k < 4; ++k)
                rv[k] = __ldg(im + (size_t)(R0 + ty * 4 + k) * HH + C0 + tx);
        }

        for (int kk = 0; kk < nim; ++kk) {
            #pragma unroll
            for (int k = 0; k < 4; ++k)
                tile[ty * 4 + k][tx] = rv[k];
            __syncthreads();

            float w[4];
            #pragma unroll
            for (int k = 0; k < 4; ++k)
                w[k] = tile[tx][ty * 4 + k];

            // issue next image's global loads NOW — they fly across the
            // store phase and the trailing barrier (long-scoreboard overlap)
            if (kk + 1 < nim) {
                const float* __restrict__ im = x + (size_t)(bc0 + kk + 1) * (HH * HH);
                #pragma unroll
                for (int k = 0; k < 4; ++k)
                    rv[k] = __ldg(im + (size_t)(R0 + ty * 4 + k) * HH + C0 + tx);
            }

            float* __restrict__ obase = out + (size_t)(bc0 + kk) * HR * RL;
            #pragma unroll
            for (int k = 0; k < 4; ++k) {
                const int u = ty * 4 + k;
                if (C0 >= 256) {
                    const int rr = C0 + u - 256;            // right edge ring
                    if (row >= 255 - rr && row <= 255 + rr)
                        obase[(size_t)rr * RL + 511 + row] = w[k];
                } else {
                    const int rr = 255 - (C0 + u);          // left edge ring
                    if (row >= 256 - rr && row <= 256 + rr)
                        obase[(size_t)rr * RL + 2044 - row] = w[k];
                }
            }
            __syncthreads();   // tile reusable next iteration
        }
    }
}

extern "C" void kernel_launch(void* const* d_in, const int* in_sizes, int n_in,
                              void* d_out, int out_size) {
    const float* x = (const float*)d_in[0];
    float* out = (float*)d_out;
    const int images = in_sizes[0] / (HH * HH);          // 512
    const int groups = (images + IMGS - 1) / IMGS;       // 64

    dim3 grid(2 * HR + 256, groups);   // x: 512 H tasks + 256 V tiles
    sqrl_main<<<grid, 256>>>(x, out, images);
}